// round 4
// baseline (speedup 1.0000x reference)
#include <cuda_runtime.h>
#include <math.h>

#define NN 50000
#define NE 800000
#define ETOT 850000      // NE + NN self loops
#define FIN 128
#define D1 128           // NH*HID
#define NH 4
#define HID 32
#define NC 40
#define NEG_SLOPE 0.2f
#define NBLK 196         // ceil(NN/256)

typedef unsigned long long ull;

// ---------------- scratch (device globals) ----------------
__device__ __align__(16) float g_h1[NN * D1];
__device__ __align__(16) float g_esrc1[NN * 4];
__device__ __align__(16) float g_edst1[NN * 4];
__device__ __align__(16) float g_agg1[NN * D1];
__device__ __align__(16) float g_h2[NN * NC];
__device__ float g_esrc2[NN];
__device__ float g_edst2[NN];
// global max of e_src per head (layer1) / scalar (layer2); reset protocol:
//   g_gmax1 reset by gat2 (end of pipeline) -> valid before next gemm1
//   g_gmax2 reset by scan1 (start of pipeline) -> valid before gemm2
__device__ float g_gmax1[NH] = {-1e30f, -1e30f, -1e30f, -1e30f};
__device__ float g_gmax2 = -1e30f;

// CSR scratch. g_cnt zeroed by gat2 at end of each invocation (zero at load).
__device__ int g_cnt[NN];
__device__ int g_scanincl[NN];
__device__ int g_bsum[NBLK];
__device__ int g_rowptr[NN + 1];
__device__ int g_cursor[NN];
__device__ int g_csrc[ETOT];

__device__ __forceinline__ float lrelu(float v) { return v > 0.0f ? v : NEG_SLOPE * v; }

__device__ __forceinline__ void atomicMaxF(float* addr, float v) {
    int b = __float_as_int(v);
    if (b >= 0) atomicMax((int*)addr, b);
    else        atomicMin((unsigned int*)addr, (unsigned int)b);
}
__device__ __forceinline__ void atomicMaxFShared(int* addr, float v) {
    int b = __float_as_int(v);
    if (b >= 0) atomicMax(addr, b);
    else        atomicMin((unsigned int*)addr, (unsigned int)b);
}

// packed fp32x2 FMA (SASS FFMA2) — only reachable via PTX
__device__ __forceinline__ ull ffma2(ull a, ull b, ull c) {
    ull d;
    asm("fma.rn.f32x2 %0, %1, %2, %3;" : "=l"(d) : "l"(a), "l"(b), "l"(c));
    return d;
}
__device__ __forceinline__ float2 u2f(ull u) {
    float2 f;
    asm("mov.b64 {%0, %1}, %2;" : "=f"(f.x), "=f"(f.y) : "l"(u));
    return f;
}

// ---------------- CSR build ----------------
__global__ void hist_kernel(const int* __restrict__ dst) {
    int t = blockIdx.x * blockDim.x + threadIdx.x;
    if (t * 4 >= NE) return;
    int4 d4 = __ldg((const int4*)dst + t);
    atomicAdd(&g_cnt[d4.x], 1);
    atomicAdd(&g_cnt[d4.y], 1);
    atomicAdd(&g_cnt[d4.z], 1);
    atomicAdd(&g_cnt[d4.w], 1);
}

__global__ void scan1_kernel() {
    __shared__ int s[256];
    int t = threadIdx.x;
    if (blockIdx.x == 0 && t == 0) g_gmax2 = -1e30f;   // reset for this invocation
    int i = blockIdx.x * 256 + t;
    int val = (i < NN) ? (g_cnt[i] + 1) : 0;
    s[t] = val;
    __syncthreads();
    #pragma unroll
    for (int off = 1; off < 256; off <<= 1) {
        int v = (t >= off) ? s[t - off] : 0;
        __syncthreads();
        s[t] += v;
        __syncthreads();
    }
    if (i < NN) g_scanincl[i] = s[t];
    if (t == 255) g_bsum[blockIdx.x] = s[255];
}

__global__ void scan3_kernel() {
    __shared__ int wsum[8];
    int t = threadIdx.x;
    int b = blockIdx.x;
    int lane = t & 31;
    int v = (t < b && t < NBLK) ? g_bsum[t] : 0;
    #pragma unroll
    for (int o = 16; o >= 1; o >>= 1) v += __shfl_xor_sync(0xffffffffu, v, o);
    if (lane == 0) wsum[t >> 5] = v;
    __syncthreads();
    int prefix = wsum[0] + wsum[1] + wsum[2] + wsum[3] + wsum[4] + wsum[5] + wsum[6] + wsum[7];
    int i = b * 256 + t;
    if (i < NN) {
        int rp = g_scanincl[i] - (g_cnt[i] + 1) + prefix;
        g_rowptr[i] = rp;
        g_csrc[rp] = i;
        g_cursor[i] = rp + 1;
    }
    if (i == NN) g_rowptr[NN] = ETOT;
}

__global__ void place_kernel(const int* __restrict__ src, const int* __restrict__ dst) {
    int t = blockIdx.x * blockDim.x + threadIdx.x;
    if (t * 4 >= NE) return;
    int4 s4 = __ldg((const int4*)src + t);
    int4 d4 = __ldg((const int4*)dst + t);
    int p0 = atomicAdd(&g_cursor[d4.x], 1);
    int p1 = atomicAdd(&g_cursor[d4.y], 1);
    int p2 = atomicAdd(&g_cursor[d4.z], 1);
    int p3 = atomicAdd(&g_cursor[d4.w], 1);
    g_csrc[p0] = s4.x;
    g_csrc[p1] = s4.y;
    g_csrc[p2] = s4.z;
    g_csrc[p3] = s4.w;
}

// ---------------- GEMM1 (f32x2) + logits + gmax epilogue ----------------
// dyn smem: float2 As2[64][132]  (= 67584 B); epilogue reuses it as float[64][264]
__global__ void gemm1_kernel(const float* __restrict__ A, const float* __restrict__ W,
                             const float* __restrict__ asrc, const float* __restrict__ adst) {
    extern __shared__ float2 As2[];
    __shared__ int smax[4];
    int tid = threadIdx.x;
    int brow = blockIdx.x * 64;
    if (tid < 4) smax[tid] = 0xFF800000;   // -inf bits
    #pragma unroll
    for (int p = 0; p < 8; p++) {
        int idx = tid + p * 256;
        int m = idx >> 5;
        int k4 = (idx & 31) * 4;
        int gr = brow + m;
        float4 v = (gr < NN) ? *(const float4*)(A + (size_t)gr * FIN + k4)
                             : make_float4(0.f, 0.f, 0.f, 0.f);
        float2* pp = &As2[m * 132 + k4];
        pp[0] = make_float2(v.x, v.x);
        pp[1] = make_float2(v.y, v.y);
        pp[2] = make_float2(v.z, v.z);
        pp[3] = make_float2(v.w, v.w);
    }
    __syncthreads();
    int tx = tid & 15, ty = tid >> 4;
    int c0 = tx * 8, r0 = ty * 4;
    ull acc[4][4];
    #pragma unroll
    for (int r = 0; r < 4; r++)
        #pragma unroll
        for (int c = 0; c < 4; c++) acc[r][c] = 0ULL;
    #pragma unroll 4
    for (int k = 0; k < 128; k++) {
        ulonglong2 wa = __ldg((const ulonglong2*)(W + k * D1 + c0));
        ulonglong2 wb = __ldg((const ulonglong2*)(W + k * D1 + c0 + 4));
        #pragma unroll
        for (int r = 0; r < 4; r++) {
            ull a = *(const ull*)&As2[(r0 + r) * 132 + k];
            acc[r][0] = ffma2(wa.x, a, acc[r][0]);
            acc[r][1] = ffma2(wa.y, a, acc[r][1]);
            acc[r][2] = ffma2(wb.x, a, acc[r][2]);
            acc[r][3] = ffma2(wb.y, a, acc[r][3]);
        }
    }
    __syncthreads();
    float* Sh = (float*)As2;   // [64][264]
    #pragma unroll
    for (int r = 0; r < 4; r++) {
        float o[8];
        #pragma unroll
        for (int c = 0; c < 4; c++) {
            float2 f = u2f(acc[r][c]);
            o[2 * c] = f.x; o[2 * c + 1] = f.y;
        }
        int row = brow + r0 + r;
        if (row < NN) {
            float* op = g_h1 + (size_t)row * D1 + c0;
            *(float4*)(op)     = make_float4(o[0], o[1], o[2], o[3]);
            *(float4*)(op + 4) = make_float4(o[4], o[5], o[6], o[7]);
        }
        float* sp = &Sh[(r0 + r) * 264 + c0];
        *(float4*)(sp)     = make_float4(o[0], o[1], o[2], o[3]);
        *(float4*)(sp + 4) = make_float4(o[4], o[5], o[6], o[7]);
    }
    __syncthreads();
    int wid = tid >> 5, lane = tid & 31;
    int h = lane >> 3;
    int off = (lane & 7) * 4;
    float4 a4 = *(const float4*)(asrc + h * HID + off);
    float4 d4 = *(const float4*)(adst + h * HID + off);
    #pragma unroll
    for (int rr = 0; rr < 8; rr++) {
        int row = wid * 8 + rr;
        int grow = brow + row;
        float4 hv = *(const float4*)&Sh[row * 264 + lane * 4];
        float ps = hv.x * a4.x + hv.y * a4.y + hv.z * a4.z + hv.w * a4.w;
        float pd = hv.x * d4.x + hv.y * d4.y + hv.z * d4.z + hv.w * d4.w;
        #pragma unroll
        for (int o = 4; o >= 1; o >>= 1) {
            ps += __shfl_xor_sync(0xffffffffu, ps, o);
            pd += __shfl_xor_sync(0xffffffffu, pd, o);
        }
        if ((lane & 7) == 0 && grow < NN) {
            g_esrc1[grow * 4 + h] = ps;
            g_edst1[grow * 4 + h] = pd;
            atomicMaxFShared(&smax[h], ps);
        }
    }
    __syncthreads();
    if (tid < 4) atomicMaxF(&g_gmax1[tid], __int_as_float(smax[tid]));
}

// ---------------- GAT layer 1: single-pass shifted softmax + aggregate + bias + ELU ----------------
__global__ void gat1_kernel(const float* __restrict__ bias) {
    int warp = (blockIdx.x * blockDim.x + threadIdx.x) >> 5;
    int lane = threadIdx.x & 31;
    if (warp >= NN) return;
    int d = warp;
    int base = g_rowptr[d];
    int end  = g_rowptr[d + 1];
    int h = lane >> 3;
    float ed_h = g_edst1[d * 4 + h];
    float S = lrelu(g_gmax1[h] + ed_h);   // upper bound of alpha over neighborhood

    float sumA = 0.f, sumB = 0.f;
    float4 accA = make_float4(0.f, 0.f, 0.f, 0.f);
    float4 accB = make_float4(0.f, 0.f, 0.f, 0.f);
    int j = base;
    for (; j + 1 < end; j += 2) {
        int s0 = g_csrc[j];
        int s1 = g_csrc[j + 1];
        float es0 = g_esrc1[s0 * 4 + h];
        float es1 = g_esrc1[s1 * 4 + h];
        float4 f0 = *(const float4*)(g_h1 + (size_t)s0 * D1 + lane * 4);
        float4 f1 = *(const float4*)(g_h1 + (size_t)s1 * D1 + lane * 4);
        float w0 = __expf(lrelu(es0 + ed_h) - S);
        float w1 = __expf(lrelu(es1 + ed_h) - S);
        sumA += w0; sumB += w1;
        accA.x += w0 * f0.x; accA.y += w0 * f0.y; accA.z += w0 * f0.z; accA.w += w0 * f0.w;
        accB.x += w1 * f1.x; accB.y += w1 * f1.y; accB.z += w1 * f1.z; accB.w += w1 * f1.w;
    }
    if (j < end) {
        int s0 = g_csrc[j];
        float es0 = g_esrc1[s0 * 4 + h];
        float4 f0 = *(const float4*)(g_h1 + (size_t)s0 * D1 + lane * 4);
        float w0 = __expf(lrelu(es0 + ed_h) - S);
        sumA += w0;
        accA.x += w0 * f0.x; accA.y += w0 * f0.y; accA.z += w0 * f0.z; accA.w += w0 * f0.w;
    }
    float inv = 1.0f / (sumA + sumB + 1e-16f);
    float4 b = *(const float4*)(bias + lane * 4);
    float4 v;
    v.x = (accA.x + accB.x) * inv + b.x;
    v.y = (accA.y + accB.y) * inv + b.y;
    v.z = (accA.z + accB.z) * inv + b.z;
    v.w = (accA.w + accB.w) * inv + b.w;
    v.x = v.x > 0.f ? v.x : (__expf(v.x) - 1.f);
    v.y = v.y > 0.f ? v.y : (__expf(v.y) - 1.f);
    v.z = v.z > 0.f ? v.z : (__expf(v.z) - 1.f);
    v.w = v.w > 0.f ? v.w : (__expf(v.w) - 1.f);
    *(float4*)(g_agg1 + (size_t)d * D1 + lane * 4) = v;
}

// ---------------- GEMM2 (f32x2, W in smem) + logits + gmax epilogue ----------------
// dyn smem: float2 As2[64][132] (67584 B) + float Ws[128*40] (20480 B) = 88064 B
#define G2_WS_OFF 67584
__global__ void gemm2_kernel(const float* __restrict__ W,
                             const float* __restrict__ asrc, const float* __restrict__ adst) {
    extern __shared__ char smraw[];
    float2* As2 = (float2*)smraw;
    float* Ws = (float*)(smraw + G2_WS_OFF);
    __shared__ int smax2;
    int tid = threadIdx.x;
    int brow = blockIdx.x * 64;
    if (tid == 0) smax2 = 0xFF800000;
    #pragma unroll
    for (int p = 0; p < 8; p++) {
        int idx = tid + p * 256;
        int m = idx >> 5;
        int k4 = (idx & 31) * 4;
        int gr = brow + m;
        float4 v = (gr < NN) ? *(const float4*)(g_agg1 + (size_t)gr * D1 + k4)
                             : make_float4(0.f, 0.f, 0.f, 0.f);
        float2* pp = &As2[m * 132 + k4];
        pp[0] = make_float2(v.x, v.x);
        pp[1] = make_float2(v.y, v.y);
        pp[2] = make_float2(v.z, v.z);
        pp[3] = make_float2(v.w, v.w);
    }
    #pragma unroll
    for (int p = 0; p < 5; p++) {
        int idx = tid + p * 256;   // 1280 float4 = 5120 floats
        ((float4*)Ws)[idx] = __ldg((const float4*)W + idx);
    }
    __syncthreads();
    int tx = tid & 3, ty = tid >> 2;     // ty in 0..63, one row per thread
    int c0 = tx * 10;
    ull acc[5] = {0ULL, 0ULL, 0ULL, 0ULL, 0ULL};
    #pragma unroll 4
    for (int k = 0; k < 128; k++) {
        ull a = *(const ull*)&As2[ty * 132 + k];
        const float* wr = Ws + k * NC + c0;
        #pragma unroll
        for (int i = 0; i < 5; i++)
            acc[i] = ffma2(*(const ull*)(wr + 2 * i), a, acc[i]);
    }
    float o[10];
    #pragma unroll
    for (int i = 0; i < 5; i++) {
        float2 f = u2f(acc[i]);
        o[2 * i] = f.x; o[2 * i + 1] = f.y;
    }
    int grow = brow + ty;
    if (grow < NN) {
        float* op = g_h2 + (size_t)grow * NC + c0;
        #pragma unroll
        for (int i = 0; i < 5; i++)
            *(float2*)(op + 2 * i) = make_float2(o[2 * i], o[2 * i + 1]);
    }
    __syncthreads();                 // all reads of Ws/As2 done
    float* Sh = Ws;                  // reuse as [64][44]
    #pragma unroll
    for (int i = 0; i < 10; i++) Sh[ty * 44 + c0 + i] = o[i];
    __syncthreads();
    int wid = tid >> 5, lane = tid & 31;
    float a_lo = __ldg(asrc + lane);
    float d_lo = __ldg(adst + lane);
    float a_hi = (lane < 8) ? __ldg(asrc + 32 + lane) : 0.f;
    float d_hi = (lane < 8) ? __ldg(adst + 32 + lane) : 0.f;
    #pragma unroll
    for (int rr = 0; rr < 8; rr++) {
        int row = wid * 8 + rr;
        int gr2 = brow + row;
        float v0 = Sh[row * 44 + lane];
        float v1 = (lane < 8) ? Sh[row * 44 + 32 + lane] : 0.f;
        float ps = v0 * a_lo + v1 * a_hi;
        float pd = v0 * d_lo + v1 * d_hi;
        #pragma unroll
        for (int o2 = 16; o2 >= 1; o2 >>= 1) {
            ps += __shfl_xor_sync(0xffffffffu, ps, o2);
            pd += __shfl_xor_sync(0xffffffffu, pd, o2);
        }
        if (lane == 0 && gr2 < NN) {
            g_esrc2[gr2] = ps;
            g_edst2[gr2] = pd;
            atomicMaxFShared(&smax2, ps);
        }
    }
    __syncthreads();
    if (tid == 0) atomicMaxF(&g_gmax2, __int_as_float(smax2));
}

// ---------------- GAT layer 2: single-pass shifted softmax + bias + log_softmax/softmax ----------------
__global__ void gat2_kernel(const float* __restrict__ bias, float* __restrict__ out) {
    int warp = (blockIdx.x * blockDim.x + threadIdx.x) >> 5;
    int lane = threadIdx.x & 31;
    if (blockIdx.x == 0 && threadIdx.x < 4) g_gmax1[threadIdx.x] = -1e30f;  // reset for next invocation
    if (warp >= NN) return;
    int d = warp;
    if (lane == 0) g_cnt[d] = 0;   // reset histogram for next invocation
    int base = g_rowptr[d];
    int end  = g_rowptr[d + 1];
    float ed = g_edst2[d];
    float S = lrelu(g_gmax2 + ed);

    float sumA = 0.f, sumB = 0.f;
    float a0A = 0.f, a1A = 0.f, a0B = 0.f, a1B = 0.f;
    int j = base;
    for (; j + 1 < end; j += 2) {
        int s0 = g_csrc[j];
        int s1 = g_csrc[j + 1];
        float es0 = g_esrc2[s0];
        float es1 = g_esrc2[s1];
        const float* h0 = g_h2 + (size_t)s0 * NC;
        const float* h1p = g_h2 + (size_t)s1 * NC;
        float f00 = h0[lane];
        float f10 = h1p[lane];
        float f01 = (lane < 8) ? h0[32 + lane] : 0.f;
        float f11 = (lane < 8) ? h1p[32 + lane] : 0.f;
        float w0 = __expf(lrelu(es0 + ed) - S);
        float w1 = __expf(lrelu(es1 + ed) - S);
        sumA += w0; sumB += w1;
        a0A += w0 * f00; a1A += w0 * f01;
        a0B += w1 * f10; a1B += w1 * f11;
    }
    if (j < end) {
        int s0 = g_csrc[j];
        float es0 = g_esrc2[s0];
        const float* h0 = g_h2 + (size_t)s0 * NC;
        float w0 = __expf(lrelu(es0 + ed) - S);
        sumA += w0;
        a0A += w0 * h0[lane];
        if (lane < 8) a1A += w0 * h0[32 + lane];
    }
    float inv = 1.0f / (sumA + sumB + 1e-16f);
    float acc0 = (a0A + a0B) * inv;
    float acc1 = (a1A + a1B) * inv;

    float v0 = acc0 + __ldg(bias + lane);
    float v1 = (lane < 8) ? (acc1 + __ldg(bias + 32 + lane)) : -INFINITY;
    float m = fmaxf(v0, v1);
    #pragma unroll
    for (int o = 16; o >= 1; o >>= 1) m = fmaxf(m, __shfl_xor_sync(0xffffffffu, m, o));
    float e0 = expf(v0 - m);
    float e1 = (lane < 8) ? expf(v1 - m) : 0.f;
    float sm = e0 + e1;
    #pragma unroll
    for (int o = 16; o >= 1; o >>= 1) sm += __shfl_xor_sync(0xffffffffu, sm, o);
    float ls = logf(sm);
    float invs = 1.0f / sm;
    float* lo = out + (size_t)d * NC;
    float* so = out + (size_t)NN * NC + (size_t)d * NC;
    lo[lane] = v0 - m - ls;
    so[lane] = e0 * invs;
    if (lane < 8) {
        lo[32 + lane] = v1 - m - ls;
        so[32 + lane] = e1 * invs;
    }
}

// ---------------- launch ----------------
#define GEMM1_SMEM 67584
#define GEMM2_SMEM 88064

extern "C" void kernel_launch(void* const* d_in, const int* in_sizes, int n_in,
                              void* d_out, int out_size) {
    const float* x   = (const float*)d_in[0];
    const int*   ei  = (const int*)d_in[1];
    const float* W1  = (const float*)d_in[2];
    const float* as1 = (const float*)d_in[3];
    const float* ad1 = (const float*)d_in[4];
    const float* b1  = (const float*)d_in[5];
    const float* W2  = (const float*)d_in[6];
    const float* as2 = (const float*)d_in[7];
    const float* ad2 = (const float*)d_in[8];
    const float* b2  = (const float*)d_in[9];
    float* out = (float*)d_out;
    const int* src = ei;
    const int* dst = ei + NE;

    cudaFuncSetAttribute(gemm1_kernel, cudaFuncAttributeMaxDynamicSharedMemorySize, GEMM1_SMEM);
    cudaFuncSetAttribute(gemm2_kernel, cudaFuncAttributeMaxDynamicSharedMemorySize, GEMM2_SMEM);

    hist_kernel<<<782, 256>>>(dst);
    scan1_kernel<<<NBLK, 256>>>();
    scan3_kernel<<<NBLK, 256>>>();
    place_kernel<<<782, 256>>>(src, dst);
    gemm1_kernel<<<782, 256, GEMM1_SMEM>>>(x, W1, as1, ad1);
    gat1_kernel<<<6250, 256>>>(b1);
    gemm2_kernel<<<782, 256, GEMM2_SMEM>>>(W2, as2, ad2);
    gat2_kernel<<<6250, 256>>>(b2, out);
}

// round 5
// speedup vs baseline: 1.1442x; 1.1442x over previous
#include <cuda_runtime.h>
#include <cuda_fp16.h>
#include <math.h>

#define NN 50000
#define NE 800000
#define ETOT 850000      // NE + NN self loops
#define FIN 128
#define D1 128           // NH*HID
#define NH 4
#define HID 32
#define NC 40
#define NEG_SLOPE 0.2f
#define CSRB 592         // persistent CSR blocks (4 per SM, all co-resident)

// ---------------- scratch (device globals) ----------------
__device__ __align__(16) __half2 g_h1h[NN * 64];     // x@W1 in fp16 (gather stream)
__device__ __align__(16) float g_esrc1[NN * 4];
__device__ __align__(16) float g_edst1[NN * 4];
__device__ __align__(16) float g_agg1[NN * D1];      // layer1 out fp32 (GEMM2 A)
__device__ __align__(16) __half g_h2h[NN * NC];      // h@W2 in fp16 (gather stream)
__device__ float g_esrc2[NN];
__device__ float g_edst2[NN];
// global max of e_src; reset protocol:
//   g_gmax1 reset by gat2 (end of pipeline); g_gmax2 reset by csr_kernel (start)
__device__ float g_gmax1[NH] = {-1e30f, -1e30f, -1e30f, -1e30f};
__device__ float g_gmax2 = -1e30f;

// CSR scratch. g_cnt and g_bar zeroed by gat2 at end of each invocation
// (and zero-initialized at load).
__device__ int g_cnt[NN];
__device__ int g_bsum[CSRB];
__device__ int g_rowptr[NN + 1];
__device__ int g_cursor[NN];
__device__ int g_csrc[ETOT];
__device__ int g_bar[3];

__device__ __forceinline__ float lrelu(float v) { return v > 0.0f ? v : NEG_SLOPE * v; }

__device__ __forceinline__ void atomicMaxF(float* addr, float v) {
    int b = __float_as_int(v);
    if (b >= 0) atomicMax((int*)addr, b);
    else        atomicMin((unsigned int*)addr, (unsigned int)b);
}
__device__ __forceinline__ void atomicMaxFShared(int* addr, float v) {
    int b = __float_as_int(v);
    if (b >= 0) atomicMax(addr, b);
    else        atomicMin((unsigned int*)addr, (unsigned int)b);
}

// grid barrier for the persistent CSR kernel (all CSRB blocks co-resident)
__device__ __forceinline__ void gridbar(int idx) {
    __syncthreads();
    if (threadIdx.x == 0) {
        __threadfence();
        atomicAdd(&g_bar[idx], 1);
        while (((volatile int*)g_bar)[idx] < CSRB) __nanosleep(64);
        __threadfence();
    }
    __syncthreads();
}

// ---------------- persistent CSR build: hist -> scan -> place ----------------
__global__ void __launch_bounds__(256, 4) csr_kernel(const int* __restrict__ src,
                                                     const int* __restrict__ dst) {
    int tid = threadIdx.x;
    int gtid = blockIdx.x * 256 + tid;
    if (blockIdx.x == 0 && tid == 0) g_gmax2 = -1e30f;

    // phase 1: histogram of dst
    for (int e = gtid; e < NE; e += CSRB * 256)
        atomicAdd(&g_cnt[__ldg(dst + e)], 1);
    gridbar(0);

    // phase 2: block-local inclusive scan of (cnt+1), block sums to g_bsum
    __shared__ int s[256];
    __shared__ int wsum[8];
    int i = gtid;
    int val = (i < NN) ? (__ldcg(&g_cnt[i]) + 1) : 0;
    s[tid] = val;
    __syncthreads();
    #pragma unroll
    for (int off = 1; off < 256; off <<= 1) {
        int v = (tid >= off) ? s[tid - off] : 0;
        __syncthreads();
        s[tid] += v;
        __syncthreads();
    }
    int incl = s[tid];
    if (tid == 255) g_bsum[blockIdx.x] = incl;
    gridbar(1);

    // phase 3: cross-block prefix; emit rowptr/cursor/self-loop
    {
        int acc = 0;
        for (int k = tid; k < blockIdx.x; k += 256) acc += __ldcg(&g_bsum[k]);
        int lane = tid & 31;
        #pragma unroll
        for (int o = 16; o >= 1; o >>= 1) acc += __shfl_xor_sync(0xffffffffu, acc, o);
        if (lane == 0) wsum[tid >> 5] = acc;
        __syncthreads();
        int prefix = wsum[0] + wsum[1] + wsum[2] + wsum[3]
                   + wsum[4] + wsum[5] + wsum[6] + wsum[7];
        if (i < NN) {
            int rp = prefix + incl - val;
            g_rowptr[i] = rp;
            g_csrc[rp] = i;          // self loop in slot 0
            g_cursor[i] = rp + 1;
        }
        if (i == NN) g_rowptr[NN] = ETOT;
    }
    gridbar(2);

    // phase 4: place edges
    for (int e = gtid; e < NE; e += CSRB * 256) {
        int dd = __ldg(dst + e);
        int ss = __ldg(src + e);
        int pos = atomicAdd(&g_cursor[dd], 1);
        g_csrc[pos] = ss;
    }
}

// ---------------- GEMM1 + logits + gmax epilogue (plain FFMA, R3 tiling) ----------------
__global__ void gemm1_kernel(const float* __restrict__ A, const float* __restrict__ W,
                             const float* __restrict__ asrc, const float* __restrict__ adst) {
    __shared__ float As[64][132];
    __shared__ int smax[4];
    int tid = threadIdx.x;
    int brow = blockIdx.x * 64;
    if (tid < 4) smax[tid] = 0xFF800000;   // -inf bits
    #pragma unroll
    for (int p = 0; p < 8; p++) {
        int idx = tid + p * 256;
        int m = idx >> 5;
        int k4 = (idx & 31) * 4;
        int gr = brow + m;
        float4 v = (gr < NN) ? *(const float4*)(A + (size_t)gr * FIN + k4)
                             : make_float4(0.f, 0.f, 0.f, 0.f);
        As[m][k4 + 0] = v.x; As[m][k4 + 1] = v.y; As[m][k4 + 2] = v.z; As[m][k4 + 3] = v.w;
    }
    __syncthreads();
    int tx = tid & 15, ty = tid >> 4;
    int c0 = tx * 8, r0 = ty * 4;
    float acc[4][8];
    #pragma unroll
    for (int j = 0; j < 4; j++)
        #pragma unroll
        for (int i = 0; i < 8; i++) acc[j][i] = 0.0f;
    #pragma unroll 4
    for (int k = 0; k < 128; k++) {
        float a0 = As[r0][k], a1 = As[r0 + 1][k], a2 = As[r0 + 2][k], a3 = As[r0 + 3][k];
        float4 wa = __ldg((const float4*)(W + k * D1 + c0));
        float4 wb = __ldg((const float4*)(W + k * D1 + c0 + 4));
        float wv[8] = {wa.x, wa.y, wa.z, wa.w, wb.x, wb.y, wb.z, wb.w};
        #pragma unroll
        for (int i = 0; i < 8; i++) {
            acc[0][i] += a0 * wv[i];
            acc[1][i] += a1 * wv[i];
            acc[2][i] += a2 * wv[i];
            acc[3][i] += a3 * wv[i];
        }
    }
    // write h1 to global as fp16 (16B per thread-row: 8 halves)
    #pragma unroll
    for (int j = 0; j < 4; j++) {
        int row = brow + r0 + j;
        if (row < NN) {
            __half2 p0 = __floats2half2_rn(acc[j][0], acc[j][1]);
            __half2 p1 = __floats2half2_rn(acc[j][2], acc[j][3]);
            __half2 p2 = __floats2half2_rn(acc[j][4], acc[j][5]);
            __half2 p3 = __floats2half2_rn(acc[j][6], acc[j][7]);
            uint4 u = make_uint4(*(unsigned*)&p0, *(unsigned*)&p1,
                                 *(unsigned*)&p2, *(unsigned*)&p3);
            *(uint4*)(g_h1h + (size_t)row * 64 + tx * 4) = u;
        }
    }
    // stage fp32 tile into smem for attention-logit epilogue
    __syncthreads();
    #pragma unroll
    for (int j = 0; j < 4; j++)
        #pragma unroll
        for (int i = 0; i < 8; i++) As[r0 + j][c0 + i] = acc[j][i];
    __syncthreads();
    int wid = tid >> 5, lane = tid & 31;
    int h = lane >> 3;
    int off = (lane & 7) * 4;
    float4 a4 = *(const float4*)(asrc + h * HID + off);
    float4 d4 = *(const float4*)(adst + h * HID + off);
    #pragma unroll
    for (int rr = 0; rr < 8; rr++) {
        int row = wid * 8 + rr;
        int grow = brow + row;
        float4 hv = *(const float4*)(&As[row][lane * 4]);
        float ps = hv.x * a4.x + hv.y * a4.y + hv.z * a4.z + hv.w * a4.w;
        float pd = hv.x * d4.x + hv.y * d4.y + hv.z * d4.z + hv.w * d4.w;
        #pragma unroll
        for (int o = 4; o >= 1; o >>= 1) {
            ps += __shfl_xor_sync(0xffffffffu, ps, o);
            pd += __shfl_xor_sync(0xffffffffu, pd, o);
        }
        if ((lane & 7) == 0 && grow < NN) {
            g_esrc1[grow * 4 + h] = ps;
            g_edst1[grow * 4 + h] = pd;
            atomicMaxFShared(&smax[h], ps);
        }
    }
    __syncthreads();
    if (tid < 4) atomicMaxF(&g_gmax1[tid], __int_as_float(smax[tid]));
}

// ---------------- GAT layer 1: single-pass shifted softmax + fp16 gather ----------------
__global__ void gat1_kernel(const float* __restrict__ bias) {
    int warp = (blockIdx.x * blockDim.x + threadIdx.x) >> 5;
    int lane = threadIdx.x & 31;
    if (warp >= NN) return;
    int d = warp;
    int base = g_rowptr[d];
    int end  = g_rowptr[d + 1];
    int h = lane >> 3;
    float ed_h = g_edst1[d * 4 + h];
    float S = lrelu(g_gmax1[h] + ed_h);   // upper bound of alpha over neighborhood

    float sumA = 0.f, sumB = 0.f;
    float4 accA = make_float4(0.f, 0.f, 0.f, 0.f);
    float4 accB = make_float4(0.f, 0.f, 0.f, 0.f);
    int j = base;
    for (; j + 1 < end; j += 2) {
        int s0 = g_csrc[j];
        int s1 = g_csrc[j + 1];
        float es0 = g_esrc1[s0 * 4 + h];
        float es1 = g_esrc1[s1 * 4 + h];
        uint2 r0 = *(const uint2*)(g_h1h + (size_t)s0 * 64 + lane * 2);
        uint2 r1 = *(const uint2*)(g_h1h + (size_t)s1 * 64 + lane * 2);
        float2 p00 = __half22float2(*(__half2*)&r0.x);
        float2 p01 = __half22float2(*(__half2*)&r0.y);
        float2 p10 = __half22float2(*(__half2*)&r1.x);
        float2 p11 = __half22float2(*(__half2*)&r1.y);
        float w0 = __expf(lrelu(es0 + ed_h) - S);
        float w1 = __expf(lrelu(es1 + ed_h) - S);
        sumA += w0; sumB += w1;
        accA.x += w0 * p00.x; accA.y += w0 * p00.y; accA.z += w0 * p01.x; accA.w += w0 * p01.y;
        accB.x += w1 * p10.x; accB.y += w1 * p10.y; accB.z += w1 * p11.x; accB.w += w1 * p11.y;
    }
    if (j < end) {
        int s0 = g_csrc[j];
        float es0 = g_esrc1[s0 * 4 + h];
        uint2 r0 = *(const uint2*)(g_h1h + (size_t)s0 * 64 + lane * 2);
        float2 p00 = __half22float2(*(__half2*)&r0.x);
        float2 p01 = __half22float2(*(__half2*)&r0.y);
        float w0 = __expf(lrelu(es0 + ed_h) - S);
        sumA += w0;
        accA.x += w0 * p00.x; accA.y += w0 * p00.y; accA.z += w0 * p01.x; accA.w += w0 * p01.y;
    }
    float inv = 1.0f / (sumA + sumB + 1e-16f);
    float4 b = *(const float4*)(bias + lane * 4);
    float4 v;
    v.x = (accA.x + accB.x) * inv + b.x;
    v.y = (accA.y + accB.y) * inv + b.y;
    v.z = (accA.z + accB.z) * inv + b.z;
    v.w = (accA.w + accB.w) * inv + b.w;
    v.x = v.x > 0.f ? v.x : (__expf(v.x) - 1.f);
    v.y = v.y > 0.f ? v.y : (__expf(v.y) - 1.f);
    v.z = v.z > 0.f ? v.z : (__expf(v.z) - 1.f);
    v.w = v.w > 0.f ? v.w : (__expf(v.w) - 1.f);
    *(float4*)(g_agg1 + (size_t)d * D1 + lane * 4) = v;
}

// ---------------- GEMM2 + logits + gmax epilogue (plain FFMA, R3 tiling) ----------------
__global__ void gemm2_kernel(const float* __restrict__ W,
                             const float* __restrict__ asrc, const float* __restrict__ adst) {
    __shared__ float As[64][132];
    __shared__ int smax2;
    int tid = threadIdx.x;
    int brow = blockIdx.x * 64;
    if (tid == 0) smax2 = 0xFF800000;
    #pragma unroll
    for (int p = 0; p < 8; p++) {
        int idx = tid + p * 256;
        int m = idx >> 5;
        int k4 = (idx & 31) * 4;
        int gr = brow + m;
        float4 v = (gr < NN) ? *(const float4*)(g_agg1 + (size_t)gr * D1 + k4)
                             : make_float4(0.f, 0.f, 0.f, 0.f);
        As[m][k4 + 0] = v.x; As[m][k4 + 1] = v.y; As[m][k4 + 2] = v.z; As[m][k4 + 3] = v.w;
    }
    __syncthreads();
    int tx = tid & 7, ty = tid >> 3;
    int c0 = tx * 5, r0 = ty * 2;
    float acc[2][5];
    #pragma unroll
    for (int j = 0; j < 2; j++)
        #pragma unroll
        for (int i = 0; i < 5; i++) acc[j][i] = 0.0f;
    #pragma unroll 4
    for (int k = 0; k < 128; k++) {
        float a0 = As[r0][k], a1 = As[r0 + 1][k];
        #pragma unroll
        for (int i = 0; i < 5; i++) {
            float w = __ldg(W + k * NC + c0 + i);
            acc[0][i] += a0 * w;
            acc[1][i] += a1 * w;
        }
    }
    // write h2 to global as fp16
    #pragma unroll
    for (int j = 0; j < 2; j++) {
        int row = brow + r0 + j;
        if (row < NN) {
            __half* o = g_h2h + (size_t)row * NC + c0;
            #pragma unroll
            for (int i = 0; i < 5; i++) o[i] = __float2half(acc[j][i]);
        }
    }
    // stage fp32 tile into smem for logit epilogue
    __syncthreads();
    #pragma unroll
    for (int j = 0; j < 2; j++)
        #pragma unroll
        for (int i = 0; i < 5; i++) As[r0 + j][c0 + i] = acc[j][i];
    __syncthreads();
    int wid = tid >> 5, lane = tid & 31;
    float a_lo = __ldg(asrc + lane);
    float d_lo = __ldg(adst + lane);
    float a_hi = (lane < 8) ? __ldg(asrc + 32 + lane) : 0.f;
    float d_hi = (lane < 8) ? __ldg(adst + 32 + lane) : 0.f;
    #pragma unroll
    for (int rr = 0; rr < 8; rr++) {
        int row = wid * 8 + rr;
        int grow = brow + row;
        float v0 = As[row][lane];
        float v1 = (lane < 8) ? As[row][32 + lane] : 0.f;
        float ps = v0 * a_lo + v1 * a_hi;
        float pd = v0 * d_lo + v1 * d_hi;
        #pragma unroll
        for (int o = 16; o >= 1; o >>= 1) {
            ps += __shfl_xor_sync(0xffffffffu, ps, o);
            pd += __shfl_xor_sync(0xffffffffu, pd, o);
        }
        if (lane == 0 && grow < NN) {
            g_esrc2[grow] = ps;
            g_edst2[grow] = pd;
            atomicMaxFShared(&smax2, ps);
        }
    }
    __syncthreads();
    if (tid == 0) atomicMaxF(&g_gmax2, __int_as_float(smax2));
}

// ---------------- GAT layer 2: shifted softmax + fp16 gather + log_softmax/softmax ----------------
__global__ void gat2_kernel(const float* __restrict__ bias, float* __restrict__ out) {
    int warp = (blockIdx.x * blockDim.x + threadIdx.x) >> 5;
    int lane = threadIdx.x & 31;
    if (blockIdx.x == 0) {
        if (threadIdx.x < 4) g_gmax1[threadIdx.x] = -1e30f;          // reset for next invocation
        else if (threadIdx.x < 7) g_bar[threadIdx.x - 4] = 0;         // reset grid barriers
    }
    if (warp >= NN) return;
    int d = warp;
    if (lane == 0) g_cnt[d] = 0;   // reset histogram for next invocation
    int base = g_rowptr[d];
    int end  = g_rowptr[d + 1];
    float ed = g_edst2[d];
    float S = lrelu(g_gmax2 + ed);

    float sumA = 0.f, sumB = 0.f;
    float a0A = 0.f, a1A = 0.f, a0B = 0.f, a1B = 0.f;
    int j = base;
    for (; j + 1 < end; j += 2) {
        int s0 = g_csrc[j];
        int s1 = g_csrc[j + 1];
        float es0 = g_esrc2[s0];
        float es1 = g_esrc2[s1];
        const __half* h0 = g_h2h + (size_t)s0 * NC;
        const __half* h1p = g_h2h + (size_t)s1 * NC;
        float f00 = __half2float(h0[lane]);
        float f10 = __half2float(h1p[lane]);
        float f01 = (lane < 8) ? __half2float(h0[32 + lane]) : 0.f;
        float f11 = (lane < 8) ? __half2float(h1p[32 + lane]) : 0.f;
        float w0 = __expf(lrelu(es0 + ed) - S);
        float w1 = __expf(lrelu(es1 + ed) - S);
        sumA += w0; sumB += w1;
        a0A += w0 * f00; a1A += w0 * f01;
        a0B += w1 * f10; a1B += w1 * f11;
    }
    if (j < end) {
        int s0 = g_csrc[j];
        float es0 = g_esrc2[s0];
        const __half* h0 = g_h2h + (size_t)s0 * NC;
        float w0 = __expf(lrelu(es0 + ed) - S);
        sumA += w0;
        a0A += w0 * __half2float(h0[lane]);
        if (lane < 8) a1A += w0 * __half2float(h0[32 + lane]);
    }
    float inv = 1.0f / (sumA + sumB + 1e-16f);
    float acc0 = (a0A + a0B) * inv;
    float acc1 = (a1A + a1B) * inv;

    float v0 = acc0 + __ldg(bias + lane);
    float v1 = (lane < 8) ? (acc1 + __ldg(bias + 32 + lane)) : -INFINITY;
    float m = fmaxf(v0, v1);
    #pragma unroll
    for (int o = 16; o >= 1; o >>= 1) m = fmaxf(m, __shfl_xor_sync(0xffffffffu, m, o));
    float e0 = expf(v0 - m);
    float e1 = (lane < 8) ? expf(v1 - m) : 0.f;
    float sm = e0 + e1;
    #pragma unroll
    for (int o = 16; o >= 1; o >>= 1) sm += __shfl_xor_sync(0xffffffffu, sm, o);
    float ls = logf(sm);
    float invs = 1.0f / sm;
    float* lo = out + (size_t)d * NC;
    float* so = out + (size_t)NN * NC + (size_t)d * NC;
    lo[lane] = v0 - m - ls;
    so[lane] = e0 * invs;
    if (lane < 8) {
        lo[32 + lane] = v1 - m - ls;
        so[32 + lane] = e1 * invs;
    }
}

// ---------------- launch ----------------
extern "C" void kernel_launch(void* const* d_in, const int* in_sizes, int n_in,
                              void* d_out, int out_size) {
    const float* x   = (const float*)d_in[0];
    const int*   ei  = (const int*)d_in[1];
    const float* W1  = (const float*)d_in[2];
    const float* as1 = (const float*)d_in[3];
    const float* ad1 = (const float*)d_in[4];
    const float* b1  = (const float*)d_in[5];
    const float* W2  = (const float*)d_in[6];
    const float* as2 = (const float*)d_in[7];
    const float* ad2 = (const float*)d_in[8];
    const float* b2  = (const float*)d_in[9];
    float* out = (float*)d_out;
    const int* src = ei;
    const int* dst = ei + NE;

    csr_kernel<<<CSRB, 256>>>(src, dst);
    gemm1_kernel<<<782, 256>>>(x, W1, as1, ad1);
    gat1_kernel<<<6250, 256>>>(b1);
    gemm2_kernel<<<782, 256>>>(W2, as2, ad2);
    gat2_kernel<<<6250, 256>>>(b2, out);
}